// round 12
// baseline (speedup 1.0000x reference)
#include <cuda_runtime.h>
#include <cuda_fp16.h>
#include <math.h>
#include <float.h>
#include <stdint.h>

// Shapes (fixed): z_e [32,64,64,64] f32, emb [512,64] f32.
#define N_TOK    131072
#define HW       4096
#define OFF_SCAL 8388608
#define OFF_IDX  8388613
#define ESCALE   1024.0f
#define EINV     (1.0f / 1024.0f)

// Scratch (static device globals: allocation-free).
// g_bh: per code 64 fp16 of (1024*e), one 128B row, 16B units XOR-swizzled by (code&7).
__device__ __align__(16) uint32_t g_bh[512 * 32];
__device__ float        g_bnorm[512];
__device__ float        g_e2max2;    // max_k ||e - fp16(1024e)/1024||^2
__device__ int          g_idx[N_TOK];
__device__ unsigned int g_counts[512];
__device__ double       g_dsum;
__device__ int          g_nflag;
__device__ int          g_flag[N_TOK];

// ---------------- helpers ----------------
__device__ __forceinline__ uint32_t smem_u32(const void* p) {
    uint32_t a;
    asm("{ .reg .u64 t; cvta.to.shared.u64 t, %1; cvt.u32.u64 %0, t; }"
        : "=r"(a) : "l"(p));
    return a;
}
__device__ __forceinline__ uint32_t packh(float lo, float hi) {
    uint32_t r;
    asm("cvt.rn.f16x2.f32 %0, %1, %2;" : "=r"(r) : "f"(hi), "f"(lo));
    return r;
}
__device__ __forceinline__ void ldsm4(uint32_t b[4], uint32_t addr) {
    asm volatile("ldmatrix.sync.aligned.m8n8.x4.shared.b16 {%0,%1,%2,%3}, [%4];"
                 : "=r"(b[0]), "=r"(b[1]), "=r"(b[2]), "=r"(b[3]) : "r"(addr));
}
__device__ __forceinline__ void mma16816(float c[4], const uint32_t a[4],
                                         uint32_t b0, uint32_t b1) {
    asm volatile("mma.sync.aligned.m16n8k16.row.col.f32.f16.f16.f32 "
                 "{%0,%1,%2,%3}, {%4,%5,%6,%7}, {%8,%9}, {%0,%1,%2,%3};"
                 : "+f"(c[0]), "+f"(c[1]), "+f"(c[2]), "+f"(c[3])
                 : "r"(a[0]), "r"(a[1]), "r"(a[2]), "r"(a[3]), "r"(b0), "r"(b1));
}

// ---- prep: code norms, residual max (for theta), swizzled fp16 codebook ----
__global__ void vq_prep(const float* __restrict__ emb) {
    int k = blockIdx.x * 256 + threadIdx.x;   // 0..511
    const float* e = emb + k * 64;
    float s = 0.f, n2 = 0.f;
    for (int d = 0; d < 64; ++d) {
        float v = e[d];
        float h = __half2float(__float2half(ESCALE * v)) * EINV;
        float r = v - h;
        s  = fmaf(v, v, s);
        n2 = fmaf(r, r, n2);
    }
    g_bnorm[k]  = s;
    g_counts[k] = 0u;
    atomicMax((int*)&g_e2max2, __float_as_int(n2));  // >=0 floats: int-max == fp-max
    if (k == 0) { g_dsum = 0.0; g_nflag = 0; }

    int sw = k & 7;
    for (int u = 0; u < 8; ++u) {                 // 8 x 16B units per 128B row
        uint32_t* dh = g_bh + k * 32 + (u ^ sw) * 4;
        for (int w = 0; w < 4; ++w)
            dh[w] = packh(ESCALE * e[8 * u + 2 * w], ESCALE * e[8 * u + 2 * w + 1]);
    }
}

// ------------- screening kernel (fp16 2-split z, single B, K=128 eff.) -------------
// smem: phase1 A-stage f32 [64][260] at 0 (66560 B); phase2 B fp16 at 0 (65536 B);
//       bn at 66560, hist at 68608. Padded to 135168 to force 1 CTA/SM (R10 env).
#define SM_BN    66560
#define SM_HIST  68608
#define SM_TOTAL 135168

__global__ __launch_bounds__(512, 1)
void vq_screen(const float* __restrict__ z_e, float* __restrict__ out) {
    extern __shared__ __align__(16) unsigned char smem[];
    const uint32_t sb = smem_u32(smem);
    const int tid  = threadIdx.x;
    const int wid  = tid >> 5, lane = tid & 31;
    const int q    = lane >> 2;          // row within 8
    const int c2   = (lane & 3) * 2;     // col pair base
    const int strip = wid * 16;          // 16 tokens per warp

    const int nbase = blockIdx.x * 256;
    const float* zb = z_e + ((size_t)(nbase >> 12) << 18) + (nbase & (HW - 1));

    // --- phase 1: coalesced z copy into padded f32 stage [d][tok], pitch 260 ---
    float* sA = (float*)smem;
#pragma unroll
    for (int t = 0; t < 8; ++t) {
        int lin = t * 512 + tid;          // 4096 float4s
        int d   = lin >> 6;
        int t4  = lin & 63;
        float4 v = *(const float4*)(zb + (size_t)d * HW + t4 * 4);
        *(float4*)(sA + d * 260 + t4 * 4) = v;
    }
    ((float*)(smem + SM_BN))[tid]      = g_bnorm[tid];
    ((uint32_t*)(smem + SM_HIST))[tid] = 0u;
    __syncthreads();

    // --- build fp16 2-split A fragments + token norms (conflict-free LDS) ---
    // A fragment (m16n8k16 row-major): a0=(row q, k lo), a1=(row q+8, k lo),
    //                                  a2=(row q, k hi), a3=(row q+8, k hi)
    uint32_t z1f[4][4], z2f[4][4];
    float    anr[2];
    {
        int r0 = strip + q, r1 = strip + q + 8;
        float a0 = 0.f, a1 = 0.f;
#pragma unroll
        for (int s = 0; s < 4; ++s) {
            int d0 = 16 * s + c2;
            float v0 = sA[(d0    ) * 260 + r0];
            float v1 = sA[(d0 + 1) * 260 + r0];
            float w0 = sA[(d0    ) * 260 + r1];
            float w1 = sA[(d0 + 1) * 260 + r1];
            float v2 = sA[(d0 + 8) * 260 + r0];
            float v3 = sA[(d0 + 9) * 260 + r0];
            float w2 = sA[(d0 + 8) * 260 + r1];
            float w3 = sA[(d0 + 9) * 260 + r1];
            a0 = fmaf(v0, v0, a0); a0 = fmaf(v1, v1, a0);
            a0 = fmaf(v2, v2, a0); a0 = fmaf(v3, v3, a0);
            a1 = fmaf(w0, w0, a1); a1 = fmaf(w1, w1, a1);
            a1 = fmaf(w2, w2, a1); a1 = fmaf(w3, w3, a1);
            float h0 = __half2float(__float2half(v0));
            float h1 = __half2float(__float2half(v1));
            float g0 = __half2float(__float2half(w0));
            float g1 = __half2float(__float2half(w1));
            float h2 = __half2float(__float2half(v2));
            float h3 = __half2float(__float2half(v3));
            float g2 = __half2float(__float2half(w2));
            float g3 = __half2float(__float2half(w3));
            z1f[s][0] = packh(h0, h1);
            z1f[s][1] = packh(g0, g1);
            z1f[s][2] = packh(h2, h3);
            z1f[s][3] = packh(g2, g3);
            z2f[s][0] = packh(v0 - h0, v1 - h1);
            z2f[s][1] = packh(w0 - g0, w1 - g1);
            z2f[s][2] = packh(v2 - h2, v3 - h3);
            z2f[s][3] = packh(w2 - g2, w3 - g3);
        }
        a0 += __shfl_xor_sync(0xffffffffu, a0, 1);
        a0 += __shfl_xor_sync(0xffffffffu, a0, 2);
        a1 += __shfl_xor_sync(0xffffffffu, a1, 1);
        a1 += __shfl_xor_sync(0xffffffffu, a1, 2);
        anr[0] = a0; anr[1] = a1;
    }
    __syncthreads();

    // --- phase 2: B fp16 tile (pre-swizzled, 64 KB) into smem ---
    {
        const uint4* src = (const uint4*)g_bh;
        uint4*       dst = (uint4*)smem;
        for (int i = tid; i < 4096; i += 512) dst[i] = src[i];
    }
    __syncthreads();

    // --- per-lane ldmatrix addressing ---
    const int sub = (lane >> 3) & 1;                    // k-half
    const int rc  = ((lane & 16) >> 1) + (lane & 7);    // code row within 16
    const int sw7 = lane & 7;
    uint32_t boff[4];
#pragma unroll
    for (int ks = 0; ks < 4; ++ks)
        boff[ks] = (uint32_t)(((2 * ks + sub) ^ sw7) << 4);

    const float* bn = (const float*)(smem + SM_BN);
    float d1[2] = {FLT_MAX, FLT_MAX};
    float d2[2] = {FLT_MAX, FLT_MAX};
    int   i1[2] = {0, 0};

#pragma unroll 1
    for (int j = 0; j < 32; ++j) {      // 32 groups of 16 codes
        uint32_t bj = sb + (uint32_t)(j * 16 + rc) * 128u;
        float c[4][2][4];               // 4 rotating accs x 2 n-tiles -> 8 chains
#pragma unroll
        for (int a = 0; a < 4; ++a)
#pragma unroll
            for (int nt = 0; nt < 2; ++nt)
#pragma unroll
                for (int r = 0; r < 4; ++r) c[a][nt][r] = 0.f;

#pragma unroll
        for (int ks = 0; ks < 4; ++ks) {
            uint32_t bh[4];
            ldsm4(bh, bj + boff[ks]);                   // B fragment reused by both halves
            int a0 = (2 * ks    ) & 3;
            int a1 = (2 * ks + 1) & 3;
            mma16816(c[a0][0], z1f[ks], bh[0], bh[1]);  // z1 . e1
            mma16816(c[a0][1], z1f[ks], bh[2], bh[3]);
            mma16816(c[a1][0], z2f[ks], bh[0], bh[1]);  // z2 . e1
            mma16816(c[a1][1], z2f[ks], bh[2], bh[3]);
        }

        int cb = j * 16 + c2;
#pragma unroll
        for (int nt = 0; nt < 2; ++nt) {
            float s0 = (c[0][nt][0] + c[1][nt][0]) + (c[2][nt][0] + c[3][nt][0]);
            float s1 = (c[0][nt][1] + c[1][nt][1]) + (c[2][nt][1] + c[3][nt][1]);
            float s2 = (c[0][nt][2] + c[1][nt][2]) + (c[2][nt][2] + c[3][nt][2]);
            float s3 = (c[0][nt][3] + c[1][nt][3]) + (c[2][nt][3] + c[3][nt][3]);
            int k0 = cb + nt * 8, k1 = k0 + 1;
            float bn0 = bn[k0], bn1 = bn[k1];
            // C fragment: {c0,c1} = row q cols {k0,k1}; {c2,c3} = row q+8 cols {k0,k1}
            // dot is scaled by 1024 -> fold 1/1024 into the -2 factor (exact pow2)
            float v0 = fmaf(s0, -2.f * EINV, anr[0] + bn0);   // row q,   code k0
            float v1 = fmaf(s1, -2.f * EINV, anr[0] + bn1);   // row q,   code k1
            float v2 = fmaf(s2, -2.f * EINV, anr[1] + bn0);   // row q+8, code k0
            float v3 = fmaf(s3, -2.f * EINV, anr[1] + bn1);   // row q+8, code k1
            if (v0 < d1[0]) { d2[0] = d1[0]; d1[0] = v0; i1[0] = k0; } else if (v0 < d2[0]) d2[0] = v0;
            if (v1 < d1[0]) { d2[0] = d1[0]; d1[0] = v1; i1[0] = k1; } else if (v1 < d2[0]) d2[0] = v1;
            if (v2 < d1[1]) { d2[1] = d1[1]; d1[1] = v2; i1[1] = k0; } else if (v2 < d2[1]) d2[1] = v2;
            if (v3 < d1[1]) { d2[1] = d1[1]; d1[1] = v3; i1[1] = k1; } else if (v3 < d2[1]) d2[1] = v3;
        }
    }

    // --- merge top-2 across quad lanes; flag near-ties; emit the rest ---
    const float e2max = sqrtf(g_e2max2);
    float dloc = 0.f;
#pragma unroll
    for (int r = 0; r < 2; ++r) {
#pragma unroll
        for (int o = 1; o <= 2; o <<= 1) {
            float od1 = __shfl_xor_sync(0xffffffffu, d1[r], o);
            int   oi1 = __shfl_xor_sync(0xffffffffu, i1[r], o);
            float od2 = __shfl_xor_sync(0xffffffffu, d2[r], o);
            if (od1 < d1[r] || (od1 == d1[r] && oi1 < i1[r])) {
                d2[r] = fminf(d1[r], od2);
                d1[r] = od1; i1[r] = oi1;
            } else {
                d2[r] = fminf(d2[r], od1);
            }
        }
        if ((lane & 3) == 0) {
            int n = nbase + strip + q + r * 8;
            // screen-vs-exact bound: z residual term is ~1e-8 (fp16 2-split);
            // |z.e2| <= sqrt(A)*E2MAX dominates. Slack covers accum + subnormal flush.
            float theta = 2.05f * sqrtf(fmaxf(anr[r], 0.f)) * e2max + 1e-5f;
            if (d2[r] - d1[r] < theta) {
                int pos = atomicAdd(&g_nflag, 1);
                g_flag[pos] = n;
            } else {
                g_idx[n]         = i1[r];
                out[OFF_IDX + n] = (float)i1[r];
                atomicAdd(((uint32_t*)(smem + SM_HIST)) + i1[r], 1u);
                dloc += d1[r];
            }
        }
    }
#pragma unroll
    for (int o = 16; o; o >>= 1) dloc += __shfl_xor_sync(0xffffffffu, dloc, o);
    if (lane == 0) atomicAdd(&g_dsum, (double)dloc);

    __syncthreads();
    {
        uint32_t h = ((uint32_t*)(smem + SM_HIST))[tid];
        if (h) atomicAdd(&g_counts[tid], h);
    }
}

// ---- exact fp32 rescan of flagged (near-tie) tokens ----
__global__ void vq_fix(const float* __restrict__ z_e, const float* __restrict__ emb,
                       float* __restrict__ out) {
    int gw   = (blockIdx.x * 256 + threadIdx.x) >> 5;
    int lane = threadIdx.x & 31;
    int nf   = g_nflag;
    for (int i = gw; i < nf; i += 4096) {
        int n = g_flag[i];
        const float* zp = z_e + ((size_t)(n >> 12) << 18) + (n & (HW - 1));
        float z[64];
        float A = 0.f;
#pragma unroll
        for (int d = 0; d < 64; ++d) {
            z[d] = zp[(size_t)d << 12];
            A = fmaf(z[d], z[d], A);
        }
        float dmin = FLT_MAX;
        int   imin = 0;
        for (int c = lane; c < 512; c += 32) {
            const float* e = emb + c * 64;
            float t0 = 0.f, t1 = 0.f, t2 = 0.f, t3 = 0.f;
#pragma unroll
            for (int d = 0; d < 64; d += 4) {
                t0 = fmaf(z[d    ], e[d    ], t0);
                t1 = fmaf(z[d + 1], e[d + 1], t1);
                t2 = fmaf(z[d + 2], e[d + 2], t2);
                t3 = fmaf(z[d + 3], e[d + 3], t3);
            }
            float dot  = (t0 + t1) + (t2 + t3);
            float dist = fmaf(dot, -2.f, A + g_bnorm[c]);
            if (dist < dmin) { dmin = dist; imin = c; }
        }
#pragma unroll
        for (int o = 16; o; o >>= 1) {
            float od = __shfl_xor_sync(0xffffffffu, dmin, o);
            int   oi = __shfl_xor_sync(0xffffffffu, imin, o);
            if (od < dmin || (od == dmin && oi < imin)) { dmin = od; imin = oi; }
        }
        if (lane == 0) {
            g_idx[n]         = imin;
            out[OFF_IDX + n] = (float)imin;
            atomicAdd(&g_counts[imin], 1u);
            atomicAdd(&g_dsum, (double)dmin);
        }
    }
}

// ---- z_q scatter: out[b,d,h,w] = emb[idx[b,h,w], d]; 4 tokens x 4 d per thread ----
__global__ void vq_zq(const float* __restrict__ emb, float* __restrict__ out) {
    int t   = blockIdx.x * 256 + threadIdx.x;   // 524288 threads
    int hw4 = (t & 1023) << 2;
    int d4  = (t >> 10) & 15;
    int b   = t >> 14;
    const int4 ix = *(const int4*)(g_idx + (b << 12) + hw4);
    float4 e0 = *(const float4*)(emb + ix.x * 64 + d4 * 4);
    float4 e1 = *(const float4*)(emb + ix.y * 64 + d4 * 4);
    float4 e2 = *(const float4*)(emb + ix.z * 64 + d4 * 4);
    float4 e3 = *(const float4*)(emb + ix.w * 64 + d4 * 4);
    int base = (b << 18) + (d4 << 14) + hw4;
    *(float4*)(out + base        ) = make_float4(e0.x, e1.x, e2.x, e3.x);
    *(float4*)(out + base +  4096) = make_float4(e0.y, e1.y, e2.y, e3.y);
    *(float4*)(out + base +  8192) = make_float4(e0.z, e1.z, e2.z, e3.z);
    *(float4*)(out + base + 12288) = make_float4(e0.w, e1.w, e2.w, e3.w);
}

// ---- scalars ----
__global__ void vq_finalize(float* __restrict__ out) {
    __shared__ float s_e[16];
    __shared__ int   s_u[16];
    int k = threadIdx.x;
    unsigned int c = g_counts[k];
    float p = (float)c * (1.0f / 131072.0f);
    float e = (c > 0) ? -p * logf(p) : 0.0f;
    int   u = (c > 0) ? 1 : 0;
#pragma unroll
    for (int o = 16; o; o >>= 1) {
        e += __shfl_xor_sync(0xffffffffu, e, o);
        u += __shfl_xor_sync(0xffffffffu, u, o);
    }
    if ((k & 31) == 0) { s_e[k >> 5] = e; s_u[k >> 5] = u; }
    __syncthreads();
    if (k == 0) {
        float ent = 0.0f; int used = 0;
        for (int i = 0; i < 16; ++i) { ent += s_e[i]; used += s_u[i]; }
        float avg = (float)(g_dsum * (1.0 / 131072.0));
        out[OFF_SCAL + 0] = 1.25f * avg;
        out[OFF_SCAL + 1] = expf(ent);
        out[OFF_SCAL + 2] = (float)used;
        out[OFF_SCAL + 3] = (float)used / 512.0f;
        out[OFF_SCAL + 4] = avg;
    }
}

extern "C" void kernel_launch(void* const* d_in, const int* in_sizes, int n_in,
                              void* d_out, int out_size) {
    const float* z_e = (const float*)d_in[0];
    const float* emb = (const float*)d_in[1];
    float*       out = (float*)d_out;

    cudaFuncSetAttribute(vq_screen, cudaFuncAttributeMaxDynamicSharedMemorySize,
                         SM_TOTAL);

    vq_prep<<<2, 256>>>(emb);
    vq_screen<<<N_TOK / 256, 512, SM_TOTAL>>>(z_e, out);
    vq_fix<<<512, 256>>>(z_e, emb, out);
    vq_zq<<<2048, 256>>>(emb, out);
    vq_finalize<<<1, 512>>>(out);
}

// round 13
// speedup vs baseline: 1.8170x; 1.8170x over previous
#include <cuda_runtime.h>
#include <math.h>
#include <float.h>
#include <stdint.h>

// Shapes (fixed): z_e [32,64,64,64] f32, emb [512,64] f32.
#define N_TOK    131072
#define HW       4096
#define OFF_SCAL 8388608
#define OFF_IDX  8388613

// Scratch (static device globals: allocation-free).
__device__ float        g_bnorm[512];
__device__ int          g_idx[N_TOK];
__device__ unsigned int g_counts[512];
__device__ double       g_dsum;

typedef unsigned long long ull;

// ---- packed f32x2 helpers (Blackwell packed fp32 pipe) ----
__device__ __forceinline__ ull fma2(ull a, ull b, ull c) {
    ull d;
    asm("fma.rn.f32x2 %0, %1, %2, %3;" : "=l"(d) : "l"(a), "l"(b), "l"(c));
    return d;
}
__device__ __forceinline__ ull add2(ull a, ull b) {
    ull d;
    asm("add.rn.f32x2 %0, %1, %2;" : "=l"(d) : "l"(a), "l"(b));
    return d;
}
__device__ __forceinline__ ull pack2(float lo, float hi) {
    ull d;
    asm("mov.b64 %0, {%1, %2};" : "=l"(d) : "f"(lo), "f"(hi));
    return d;
}
__device__ __forceinline__ float lanesum(ull s) {
    float lo, hi;
    asm("mov.b64 {%0, %1}, %2;" : "=f"(lo), "=f"(hi) : "l"(s));
    return lo + hi;
}

// ---- prep: code norms + zero accumulators ----
__global__ void vq_prep(const float* __restrict__ emb) {
    int k = blockIdx.x * 256 + threadIdx.x;     // 0..511
    const float* e = emb + k * 64;
    float s = 0.f;
#pragma unroll
    for (int d = 0; d < 64; ++d) s = fmaf(e[d], e[d], s);
    g_bnorm[k]  = s;
    g_counts[k] = 0u;
    if (k == 0) g_dsum = 0.0;
}

// ---- main: persistent CTAs, tiles of 128 tokens, 4-way code split ----
// Each thread: 2 tokens (tp, tp+64 within tile), 128 codes (quarter 'quad').
// Inner loop body identical to the proven R5 kernel (d-pairs in f32x2 lanes,
// emb rows row-major in smem, broadcast LDS.128).
// smem: s_emb f32[32768] | s_bn f32[512] | s_hist u32[512] | s_md f32[512] | s_mi i32[512]
#define SM_FLOATS 34816
#define SM_BYTES  (SM_FLOATS * 4)     // 139264

__global__ __launch_bounds__(256, 1)
void vq_main(const float* __restrict__ z_e, const float* __restrict__ emb,
             float* __restrict__ out) {
    extern __shared__ __align__(16) float sm[];
    float*        s_emb  = sm;                          // 32768 f32 (raw emb rows)
    float*        s_bn   = sm + 32768;                  // 512
    unsigned int* s_hist = (unsigned int*)(sm + 33280); // 512
    float*        s_md   = sm + 33792;                  // 512
    int*          s_mi   = (int*)(sm + 34304);          // 512
    const int tid = threadIdx.x;

    for (int i = tid; i < 8192; i += 256)
        ((float4*)s_emb)[i] = ((const float4*)emb)[i];
    for (int i = tid; i < 512; i += 256) {
        s_bn[i]   = g_bnorm[i];
        s_hist[i] = 0u;
    }
    __syncthreads();

    const int quad  = tid >> 6;          // code quarter: codes [quad*128, +128)
    const int tp    = tid & 63;          // token slot
    const int kbase = quad * 128;

    for (int tile = (int)blockIdx.x; tile < 1024; tile += 148) {
        // two tokens per thread: tile*128 + tp and + tp + 64 (both same batch b)
        const int n0 = tile * 128 + tp;
        const float* zp0 = z_e + ((size_t)(n0 >> 12) << 18) + (n0 & (HW - 1));
        const float* zp1 = zp0 + 64;

        // load both tokens, pack consecutive-d pairs, compute ||z||^2
        ull z0[32], z1[32];
        float a00 = 0.f, a01 = 0.f, a10 = 0.f, a11 = 0.f;
#pragma unroll
        for (int j = 0; j < 32; j += 2) {
            float u0 = zp0[(size_t)(2 * j + 0) << 12];
            float u1 = zp0[(size_t)(2 * j + 1) << 12];
            float u2 = zp0[(size_t)(2 * j + 2) << 12];
            float u3 = zp0[(size_t)(2 * j + 3) << 12];
            float v0 = zp1[(size_t)(2 * j + 0) << 12];
            float v1 = zp1[(size_t)(2 * j + 1) << 12];
            float v2 = zp1[(size_t)(2 * j + 2) << 12];
            float v3 = zp1[(size_t)(2 * j + 3) << 12];
            a00 = fmaf(u0, u0, a00); a00 = fmaf(u1, u1, a00);
            a01 = fmaf(u2, u2, a01); a01 = fmaf(u3, u3, a01);
            a10 = fmaf(v0, v0, a10); a10 = fmaf(v1, v1, a10);
            a11 = fmaf(v2, v2, a11); a11 = fmaf(v3, v3, a11);
            z0[j]     = pack2(u0, u1);
            z0[j + 1] = pack2(u2, u3);
            z1[j]     = pack2(v0, v1);
            z1[j + 1] = pack2(v2, v3);
        }
        const float A0 = a00 + a01;
        const float A1 = a10 + a11;

        float dmin0 = FLT_MAX, dmin1 = FLT_MAX;
        int   imin0 = 0,       imin1 = 0;
#pragma unroll 1
        for (int k = kbase; k < kbase + 128; ++k) {
            const ulonglong2* row = (const ulonglong2*)(s_emb + (k << 6));
            ull c00 = 0ull, c01 = 0ull, c10 = 0ull, c11 = 0ull;
#pragma unroll
            for (int j = 0; j < 16; j += 2) {
                ulonglong2 q0 = row[j];
                ulonglong2 q1 = row[j + 1];
                c00 = fma2(z0[2 * j + 0], q0.x, c00);
                c10 = fma2(z1[2 * j + 0], q0.x, c10);
                c01 = fma2(z0[2 * j + 1], q0.y, c01);
                c11 = fma2(z1[2 * j + 1], q0.y, c11);
                c00 = fma2(z0[2 * j + 2], q1.x, c00);
                c10 = fma2(z1[2 * j + 2], q1.x, c10);
                c01 = fma2(z0[2 * j + 3], q1.y, c01);
                c11 = fma2(z1[2 * j + 3], q1.y, c11);
            }
            float bnk  = s_bn[k];
            float dot0 = lanesum(add2(c00, c01));
            float dot1 = lanesum(add2(c10, c11));
            // replicate reference rounding: d = fl( fl(A + B) - 2*dot )
            float d0 = fmaf(dot0, -2.f, A0 + bnk);
            float d1 = fmaf(dot1, -2.f, A1 + bnk);
            if (d0 < dmin0) { dmin0 = d0; imin0 = k; }
            if (d1 < dmin1) { dmin1 = d1; imin1 = k; }
        }

        // publish per-quarter candidates
        s_md[quad * 128 + tp]      = dmin0;
        s_mi[quad * 128 + tp]      = imin0;
        s_md[quad * 128 + tp + 64] = dmin1;
        s_mi[quad * 128 + tp + 64] = imin1;
        __syncthreads();

        // merge across quarters (ascending quad = ascending code: strict < keeps
        // the lowest index on exact ties, matching the reference argmin)
        if (tid < 128) {
            float d = s_md[tid];
            int   i = s_mi[tid];
#pragma unroll
            for (int q = 1; q < 4; ++q) {
                float dq = s_md[q * 128 + tid];
                int   iq = s_mi[q * 128 + tid];
                if (dq < d) { d = dq; i = iq; }
            }
            int n = tile * 128 + tid;
            g_idx[n]         = i;
            out[OFF_IDX + n] = (float)i;
            atomicAdd(&s_hist[i], 1u);
            float v = d;
#pragma unroll
            for (int o = 16; o; o >>= 1) v += __shfl_xor_sync(0xffffffffu, v, o);
            if ((tid & 31) == 0) atomicAdd(&g_dsum, (double)v);
        }
        __syncthreads();   // protect s_md/s_mi for the next tile
    }

    // flush per-CTA histogram once
    for (int i = tid; i < 512; i += 256) {
        unsigned int c = s_hist[i];
        if (c) atomicAdd(&g_counts[i], c);
    }
}

// ---- z_q scatter: out[b,d,h,w] = emb[idx[b,h,w], d] (proven R10 version) ----
__global__ void vq_zq(const float* __restrict__ emb, float* __restrict__ out) {
    int t  = blockIdx.x * 256 + threadIdx.x;
    int hw = t & (HW - 1);
    int d4 = (t >> 12) & 15;
    int b  = t >> 16;
    int idx = g_idx[(b << 12) + hw];
    const float4 e = *(const float4*)(emb + idx * 64 + d4 * 4);
    int base = (b << 18) + (d4 << 14) + hw;
    out[base        ] = e.x;
    out[base +  4096] = e.y;
    out[base +  8192] = e.z;
    out[base + 12288] = e.w;
}

// ---- scalars ----
__global__ void vq_finalize(float* __restrict__ out) {
    __shared__ float s_e[16];
    __shared__ int   s_u[16];
    int k = threadIdx.x;
    unsigned int c = g_counts[k];
    float p = (float)c * (1.0f / 131072.0f);
    float e = (c > 0) ? -p * logf(p) : 0.0f;
    int   u = (c > 0) ? 1 : 0;
#pragma unroll
    for (int o = 16; o; o >>= 1) {
        e += __shfl_xor_sync(0xffffffffu, e, o);
        u += __shfl_xor_sync(0xffffffffu, u, o);
    }
    if ((k & 31) == 0) { s_e[k >> 5] = e; s_u[k >> 5] = u; }
    __syncthreads();
    if (k == 0) {
        float ent = 0.0f; int used = 0;
        for (int i = 0; i < 16; ++i) { ent += s_e[i]; used += s_u[i]; }
        float avg = (float)(g_dsum * (1.0 / 131072.0));
        out[OFF_SCAL + 0] = 1.25f * avg;                // loss_vq
        out[OFF_SCAL + 1] = expf(ent);                  // perplexity
        out[OFF_SCAL + 2] = (float)used;                // codes_used
        out[OFF_SCAL + 3] = (float)used / 512.0f;       // usage_ratio
        out[OFF_SCAL + 4] = avg;                        // avg_dist2
    }
}

extern "C" void kernel_launch(void* const* d_in, const int* in_sizes, int n_in,
                              void* d_out, int out_size) {
    const float* z_e = (const float*)d_in[0];
    const float* emb = (const float*)d_in[1];
    float*       out = (float*)d_out;

    cudaFuncSetAttribute(vq_main, cudaFuncAttributeMaxDynamicSharedMemorySize,
                         SM_BYTES);

    vq_prep<<<2, 256>>>(emb);
    vq_main<<<148, 256, SM_BYTES>>>(z_e, emb, out);
    vq_zq<<<(N_TOK * 16) / 256, 256>>>(emb, out);
    vq_finalize<<<1, 512>>>(out);
}

// round 14
// speedup vs baseline: 1.8172x; 1.0001x over previous
#include <cuda_runtime.h>
#include <math.h>
#include <float.h>
#include <stdint.h>

// Shapes (fixed): z_e [32,64,64,64] f32, emb [512,64] f32.
#define N_TOK    131072
#define HW       4096
#define OFF_SCAL 8388608
#define OFF_IDX  8388613

// Scratch (static device globals: allocation-free).
__device__ float        g_bnorm[512];
__device__ unsigned int g_counts[512];
__device__ double       g_dsum;
__device__ int          g_done;

typedef unsigned long long ull;

// ---- packed f32x2 helpers (Blackwell packed fp32 pipe) ----
__device__ __forceinline__ ull fma2(ull a, ull b, ull c) {
    ull d;
    asm("fma.rn.f32x2 %0, %1, %2, %3;" : "=l"(d) : "l"(a), "l"(b), "l"(c));
    return d;
}
__device__ __forceinline__ ull add2(ull a, ull b) {
    ull d;
    asm("add.rn.f32x2 %0, %1, %2;" : "=l"(d) : "l"(a), "l"(b));
    return d;
}
__device__ __forceinline__ ull pack2(float lo, float hi) {
    ull d;
    asm("mov.b64 %0, {%1, %2};" : "=l"(d) : "f"(lo), "f"(hi));
    return d;
}
__device__ __forceinline__ float lanesum(ull s) {
    float lo, hi;
    asm("mov.b64 {%0, %1}, %2;" : "=f"(lo), "=f"(hi) : "l"(s));
    return lo + hi;
}

// ---- prep: code norms + zero accumulators ----
__global__ void vq_prep(const float* __restrict__ emb) {
    int k = blockIdx.x * 256 + threadIdx.x;     // 0..511
    const float* e = emb + k * 64;
    float s = 0.f;
#pragma unroll
    for (int d = 0; d < 64; ++d) s = fmaf(e[d], e[d], s);
    g_bnorm[k]  = s;
    g_counts[k] = 0u;
    if (k == 0) { g_dsum = 0.0; g_done = 0; }
}

// ---- main: persistent CTAs; per tile: argmin (R13 k-loop) + fused z_q scatter;
//      last CTA runs the scalar finalize in-kernel. ----
// smem: s_emb f32[32768] | s_bn f32[512] | s_hist u32[512] | s_md f32[512] | s_mi i32[512]
#define SM_FLOATS 34816
#define SM_BYTES  (SM_FLOATS * 4)     // 139264

__global__ __launch_bounds__(256, 1)
void vq_main(const float* __restrict__ z_e, const float* __restrict__ emb,
             float* __restrict__ out) {
    extern __shared__ __align__(16) float sm[];
    float*        s_emb  = sm;                          // 32768 f32 (raw emb rows)
    float*        s_bn   = sm + 32768;                  // 512
    unsigned int* s_hist = (unsigned int*)(sm + 33280); // 512
    float*        s_md   = sm + 33792;                  // 512
    int*          s_mi   = (int*)(sm + 34304);          // 512
    const int tid = threadIdx.x;

    for (int i = tid; i < 8192; i += 256)
        ((float4*)s_emb)[i] = ((const float4*)emb)[i];
    for (int i = tid; i < 512; i += 256) {
        s_bn[i]   = g_bnorm[i];
        s_hist[i] = 0u;
    }
    __syncthreads();

    const int quad  = tid >> 6;          // code quarter: codes [quad*128, +128)
    const int tp    = tid & 63;          // token slot
    const int kbase = quad * 128;

    for (int tile = (int)blockIdx.x; tile < 1024; tile += 148) {
        const int n0   = tile * 128;
        const int b    = n0 >> 12;
        const int hw0  = n0 & (HW - 1);
        const float* zp0 = z_e + ((size_t)b << 18) + hw0 + tp;
        const float* zp1 = zp0 + 64;

        // load both tokens, pack consecutive-d pairs, compute ||z||^2
        ull z0[32], z1[32];
        float a00 = 0.f, a01 = 0.f, a10 = 0.f, a11 = 0.f;
#pragma unroll
        for (int j = 0; j < 32; j += 2) {
            float u0 = zp0[(size_t)(2 * j + 0) << 12];
            float u1 = zp0[(size_t)(2 * j + 1) << 12];
            float u2 = zp0[(size_t)(2 * j + 2) << 12];
            float u3 = zp0[(size_t)(2 * j + 3) << 12];
            float v0 = zp1[(size_t)(2 * j + 0) << 12];
            float v1 = zp1[(size_t)(2 * j + 1) << 12];
            float v2 = zp1[(size_t)(2 * j + 2) << 12];
            float v3 = zp1[(size_t)(2 * j + 3) << 12];
            a00 = fmaf(u0, u0, a00); a00 = fmaf(u1, u1, a00);
            a01 = fmaf(u2, u2, a01); a01 = fmaf(u3, u3, a01);
            a10 = fmaf(v0, v0, a10); a10 = fmaf(v1, v1, a10);
            a11 = fmaf(v2, v2, a11); a11 = fmaf(v3, v3, a11);
            z0[j]     = pack2(u0, u1);
            z0[j + 1] = pack2(u2, u3);
            z1[j]     = pack2(v0, v1);
            z1[j + 1] = pack2(v2, v3);
        }
        const float A0 = a00 + a01;
        const float A1 = a10 + a11;

        float dmin0 = FLT_MAX, dmin1 = FLT_MAX;
        int   imin0 = 0,       imin1 = 0;
#pragma unroll 1
        for (int k = kbase; k < kbase + 128; ++k) {
            const ulonglong2* row = (const ulonglong2*)(s_emb + (k << 6));
            ull c00 = 0ull, c01 = 0ull, c10 = 0ull, c11 = 0ull;
#pragma unroll
            for (int j = 0; j < 16; j += 2) {
                ulonglong2 q0 = row[j];
                ulonglong2 q1 = row[j + 1];
                c00 = fma2(z0[2 * j + 0], q0.x, c00);
                c10 = fma2(z1[2 * j + 0], q0.x, c10);
                c01 = fma2(z0[2 * j + 1], q0.y, c01);
                c11 = fma2(z1[2 * j + 1], q0.y, c11);
                c00 = fma2(z0[2 * j + 2], q1.x, c00);
                c10 = fma2(z1[2 * j + 2], q1.x, c10);
                c01 = fma2(z0[2 * j + 3], q1.y, c01);
                c11 = fma2(z1[2 * j + 3], q1.y, c11);
            }
            float bnk  = s_bn[k];
            float dot0 = lanesum(add2(c00, c01));
            float dot1 = lanesum(add2(c10, c11));
            // replicate reference rounding: d = fl( fl(A + B) - 2*dot )
            float d0 = fmaf(dot0, -2.f, A0 + bnk);
            float d1 = fmaf(dot1, -2.f, A1 + bnk);
            if (d0 < dmin0) { dmin0 = d0; imin0 = k; }
            if (d1 < dmin1) { dmin1 = d1; imin1 = k; }
        }

        // publish per-quarter candidates
        s_md[quad * 128 + tp]      = dmin0;
        s_mi[quad * 128 + tp]      = imin0;
        s_md[quad * 128 + tp + 64] = dmin1;
        s_mi[quad * 128 + tp + 64] = imin1;
        __syncthreads();

        // merge across quarters (ascending quad = ascending code: strict < keeps
        // the lowest index on exact ties, matching the reference argmin)
        if (tid < 128) {
            float d = s_md[tid];
            int   i = s_mi[tid];
#pragma unroll
            for (int q = 1; q < 4; ++q) {
                float dq = s_md[q * 128 + tid];
                int   iq = s_mi[q * 128 + tid];
                if (dq < d) { d = dq; i = iq; }
            }
            int n = n0 + tid;
            out[OFF_IDX + n] = (float)i;
            s_mi[tid]        = i;            // final index for the scatter phase
            atomicAdd(&s_hist[i], 1u);
            float v = d;
#pragma unroll
            for (int o = 16; o; o >>= 1) v += __shfl_xor_sync(0xffffffffu, v, o);
            if ((tid & 31) == 0) atomicAdd(&g_dsum, (double)v);
        }
        __syncthreads();

        // fused z_q scatter: 512 items (32 token-groups x 16 d4), 2 per thread.
        // item: 4 tokens' idx from smem, 4 float4 gathers from emb (L1-resident),
        // transpose, 4 coalesced float4 stores.
#pragma unroll
        for (int r = 0; r < 2; ++r) {
            int it = r * 256 + tid;
            int d4 = it >> 5;                 // 0..15 (uniform across a warp)
            int t4 = (it & 31) << 2;          // token group base 0..124
            const int4 ix = *(const int4*)(s_mi + t4);
            float4 e0 = *(const float4*)(emb + ix.x * 64 + d4 * 4);
            float4 e1 = *(const float4*)(emb + ix.y * 64 + d4 * 4);
            float4 e2 = *(const float4*)(emb + ix.z * 64 + d4 * 4);
            float4 e3 = *(const float4*)(emb + ix.w * 64 + d4 * 4);
            int base = (b << 18) + (d4 << 14) + hw0 + t4;
            *(float4*)(out + base         ) = make_float4(e0.x, e1.x, e2.x, e3.x);
            *(float4*)(out + base +  4096 ) = make_float4(e0.y, e1.y, e2.y, e3.y);
            *(float4*)(out + base +  8192 ) = make_float4(e0.z, e1.z, e2.z, e3.z);
            *(float4*)(out + base + 12288 ) = make_float4(e0.w, e1.w, e2.w, e3.w);
        }
        __syncthreads();   // protect s_md/s_mi/s_hist for the next tile
    }

    // flush per-CTA histogram once
    for (int i = tid; i < 512; i += 256) {
        unsigned int c = s_hist[i];
        if (c) atomicAdd(&g_counts[i], c);
    }
    __threadfence();
    __syncthreads();

    // ticket: the last CTA to finish runs the scalar finalize in-kernel
    if (tid == 0) s_hist[0] = (atomicAdd(&g_done, 1) == 147) ? 1u : 0u;
    __syncthreads();
    if (s_hist[0]) {
        __threadfence();
        float e = 0.f; int u = 0;
#pragma unroll
        for (int r = 0; r < 2; ++r) {
            unsigned int c = g_counts[r * 256 + tid];
            float p = (float)c * (1.0f / 131072.0f);
            if (c > 0) { e -= p * logf(p); u += 1; }
        }
#pragma unroll
        for (int o = 16; o; o >>= 1) {
            e += __shfl_xor_sync(0xffffffffu, e, o);
            u += __shfl_xor_sync(0xffffffffu, u, o);
        }
        if ((tid & 31) == 0) { s_md[tid >> 5] = e; s_mi[64 + (tid >> 5)] = u; }
        __syncthreads();
        if (tid == 0) {
            float ent = 0.f; int used = 0;
            for (int i = 0; i < 8; ++i) { ent += s_md[i]; used += s_mi[64 + i]; }
            float avg = (float)(g_dsum * (1.0 / 131072.0));
            out[OFF_SCAL + 0] = 1.25f * avg;                // loss_vq
            out[OFF_SCAL + 1] = expf(ent);                  // perplexity
            out[OFF_SCAL + 2] = (float)used;                // codes_used
            out[OFF_SCAL + 3] = (float)used / 512.0f;       // usage_ratio
            out[OFF_SCAL + 4] = avg;                        // avg_dist2
            g_done = 0;                                     // replay-safe reset
        }
    }
}

extern "C" void kernel_launch(void* const* d_in, const int* in_sizes, int n_in,
                              void* d_out, int out_size) {
    const float* z_e = (const float*)d_in[0];
    const float* emb = (const float*)d_in[1];
    float*       out = (float*)d_out;

    cudaFuncSetAttribute(vq_main, cudaFuncAttributeMaxDynamicSharedMemorySize,
                         SM_BYTES);

    vq_prep<<<2, 256>>>(emb);
    vq_main<<<148, 256, SM_BYTES>>>(z_e, emb, out);
}